// round 3
// baseline (speedup 1.0000x reference)
#include <cuda_runtime.h>
#include <math.h>
#include <stdint.h>

// Problem constants
#define B_  2
#define S_  2048
#define E_  2048
#define H_  32
#define HKV_ 8
#define D_  64
#define G_  4
#define M_  (B_*S_)   // 4096

// Scratch (device globals; no allocation allowed)
__device__ float g_Q[(size_t)B_*S_*H_*D_];      // (B,S,H,D)  32MB
__device__ float g_K[(size_t)B_*S_*HKV_*D_];    // (B,S,HKV,D) 8MB
__device__ float g_V[(size_t)B_*S_*HKV_*D_];    // 8MB
__device__ float g_A[(size_t)B_*S_*H_*D_];      // attention out, (B,S,H,D) == (B,S,E)

// ---------------------------------------------------------------------------
// SGEMM:  C[m][n] = sum_k A[m][k] * W[n][k]   (A: MxK row-major, W: NxK row-major)
// 128x128x16 tiles, 8x8 per thread, 256 threads.
// ---------------------------------------------------------------------------
__global__ __launch_bounds__(256) void gemm_nt_kernel(
    const float* __restrict__ A, const float* __restrict__ W,
    float* __restrict__ C, int M, int N, int K)
{
    const int BM = 128, BN = 128, BK = 16;
    __shared__ float As[BK][BM + 4];
    __shared__ float Bs[BK][BN + 4];

    int tid = threadIdx.x;
    int tx = tid & 15;        // n-dir
    int ty = tid >> 4;        // m-dir
    int m0 = blockIdx.y * BM;
    int n0 = blockIdx.x * BN;

    float acc[8][8];
#pragma unroll
    for (int i = 0; i < 8; i++)
#pragma unroll
        for (int j = 0; j < 8; j++) acc[i][j] = 0.f;

    for (int k0 = 0; k0 < K; k0 += BK) {
        // Load A tile: 128 rows x 16 k, 512 float4s, 2 per thread
#pragma unroll
        for (int i = 0; i < 2; i++) {
            int lin = tid + i * 256;          // float4 index
            int row = lin >> 2;
            int kc  = (lin & 3) * 4;
            float4 v = *(const float4*)(A + (size_t)(m0 + row) * K + k0 + kc);
            As[kc + 0][row] = v.x; As[kc + 1][row] = v.y;
            As[kc + 2][row] = v.z; As[kc + 3][row] = v.w;
        }
        // Load W tile: 128 n-rows x 16 k
#pragma unroll
        for (int i = 0; i < 2; i++) {
            int lin = tid + i * 256;
            int row = lin >> 2;
            int kc  = (lin & 3) * 4;
            float4 v = *(const float4*)(W + (size_t)(n0 + row) * K + k0 + kc);
            Bs[kc + 0][row] = v.x; Bs[kc + 1][row] = v.y;
            Bs[kc + 2][row] = v.z; Bs[kc + 3][row] = v.w;
        }
        __syncthreads();

#pragma unroll
        for (int kk = 0; kk < BK; kk++) {
            float a[8], b[8];
            *(float4*)(a)     = *(const float4*)&As[kk][ty * 8];
            *(float4*)(a + 4) = *(const float4*)&As[kk][ty * 8 + 4];
            *(float4*)(b)     = *(const float4*)&Bs[kk][tx * 8];
            *(float4*)(b + 4) = *(const float4*)&Bs[kk][tx * 8 + 4];
#pragma unroll
            for (int i = 0; i < 8; i++)
#pragma unroll
                for (int j = 0; j < 8; j++)
                    acc[i][j] += a[i] * b[j];
        }
        __syncthreads();
    }

#pragma unroll
    for (int i = 0; i < 8; i++) {
        float* crow = C + (size_t)(m0 + ty * 8 + i) * N + n0 + tx * 8;
        *(float4*)(crow)     = make_float4(acc[i][0], acc[i][1], acc[i][2], acc[i][3]);
        *(float4*)(crow + 4) = make_float4(acc[i][4], acc[i][5], acc[i][6], acc[i][7]);
    }
}

// ---------------------------------------------------------------------------
// RoPE in-place on (B,S,nh,D) tensor. One thread per rotation pair.
// out[d]    = t[d]*cos[s,d] - t[d+32]*sin[s,d]
// out[d+32] = t[d+32]*cos[s,d] + t[d]*sin[s,d]    (cos/sin halves identical)
// ---------------------------------------------------------------------------
__global__ void rope_kernel(float* __restrict__ T, const float* __restrict__ cosT,
                            const float* __restrict__ sinT, int nh, int total_pairs)
{
    int idx = blockIdx.x * blockDim.x + threadIdx.x;
    if (idx >= total_pairs) return;
    int d = idx & 31;
    int h = (idx >> 5) % nh;
    int s = (idx >> 5) / nh % S_;
    int b = idx / (32 * nh * S_);
    size_t base = (((size_t)b * S_ + s) * nh + h) * D_;
    float q1 = T[base + d];
    float q2 = T[base + d + 32];
    float c  = cosT[s * D_ + d];
    float sn = sinT[s * D_ + d];
    T[base + d]      = q1 * c - q2 * sn;
    T[base + d + 32] = q2 * c + q1 * sn;
}

// ---------------------------------------------------------------------------
// Flash attention, fp32, non-causal. BM=BN=64, D=64.
// grid: (S/64, H, B), block: (16,16). Each thread: 4x4 score tile + 4x4 O tile.
// ---------------------------------------------------------------------------
#define FPAD 68
__global__ __launch_bounds__(256) void flash_kernel(
    const float* __restrict__ Qg, const float* __restrict__ Kg,
    const float* __restrict__ Vg, float* __restrict__ Og)
{
    extern __shared__ float sm[];
    float* sQ = sm;                 // 64 x 68
    float* sK = sQ + 64 * FPAD;
    float* sV = sK + 64 * FPAD;
    float* sP = sV + 64 * FPAD;

    int tx = threadIdx.x;           // 0..15, key-col / d-col group
    int ty = threadIdx.y;           // 0..15, query-row group
    int tid = ty * 16 + tx;
    int q0 = blockIdx.x * 64;
    int h  = blockIdx.y;
    int b  = blockIdx.z;
    int hk = h / G_;

    const float scale = 0.125f;     // 1/sqrt(64)

    // Load Q tile (scaled): 64 rows x 64 d = 1024 float4s, 4 per thread
#pragma unroll
    for (int i = 0; i < 4; i++) {
        int lin = tid + i * 256;
        int row = lin >> 4;
        int d   = (lin & 15) * 4;
        float4 v = *(const float4*)(Qg + ((((size_t)b * S_ + q0 + row) * H_ + h) * D_) + d);
        float* dst = &sQ[row * FPAD + d];
        dst[0] = v.x * scale; dst[1] = v.y * scale;
        dst[2] = v.z * scale; dst[3] = v.w * scale;
    }

    float m[4], l[4], o[4][4];
#pragma unroll
    for (int r = 0; r < 4; r++) {
        m[r] = -INFINITY; l[r] = 0.f;
#pragma unroll
        for (int c = 0; c < 4; c++) o[r][c] = 0.f;
    }

    for (int t0 = 0; t0 < S_; t0 += 64) {
        __syncthreads();  // prior iteration's smem reads complete
        // Load K and V tiles
#pragma unroll
        for (int i = 0; i < 4; i++) {
            int lin = tid + i * 256;
            int row = lin >> 4;
            int d   = (lin & 15) * 4;
            size_t gidx = (((size_t)b * S_ + t0 + row) * HKV_ + hk) * D_ + d;
            float4 kv = *(const float4*)(Kg + gidx);
            float4 vv = *(const float4*)(Vg + gidx);
            float* dk = &sK[row * FPAD + d];
            dk[0] = kv.x; dk[1] = kv.y; dk[2] = kv.z; dk[3] = kv.w;
            float* dv = &sV[row * FPAD + d];
            dv[0] = vv.x; dv[1] = vv.y; dv[2] = vv.z; dv[3] = vv.w;
        }
        __syncthreads();

        // S = Q K^T (Q pre-scaled)
        float sacc[4][4];
#pragma unroll
        for (int r = 0; r < 4; r++)
#pragma unroll
            for (int c = 0; c < 4; c++) sacc[r][c] = 0.f;

#pragma unroll 4
        for (int d4 = 0; d4 < 16; d4++) {
            float4 qv[4], kv[4];
#pragma unroll
            for (int r = 0; r < 4; r++)
                qv[r] = *(const float4*)&sQ[(ty * 4 + r) * FPAD + d4 * 4];
#pragma unroll
            for (int c = 0; c < 4; c++)
                kv[c] = *(const float4*)&sK[(tx * 4 + c) * FPAD + d4 * 4];
#pragma unroll
            for (int r = 0; r < 4; r++)
#pragma unroll
                for (int c = 0; c < 4; c++) {
                    sacc[r][c] += qv[r].x * kv[c].x;
                    sacc[r][c] += qv[r].y * kv[c].y;
                    sacc[r][c] += qv[r].z * kv[c].z;
                    sacc[r][c] += qv[r].w * kv[c].w;
                }
        }

        // Online softmax per row (rows owned by the 16 threads sharing ty)
#pragma unroll
        for (int r = 0; r < 4; r++) {
            float mloc = sacc[r][0];
            mloc = fmaxf(mloc, sacc[r][1]);
            mloc = fmaxf(mloc, sacc[r][2]);
            mloc = fmaxf(mloc, sacc[r][3]);
#pragma unroll
            for (int off = 8; off >= 1; off >>= 1)
                mloc = fmaxf(mloc, __shfl_xor_sync(0xffffffffu, mloc, off, 16));
            float mnew  = fmaxf(m[r], mloc);
            float alpha = __expf(m[r] - mnew);
            float lloc = 0.f;
#pragma unroll
            for (int c = 0; c < 4; c++) {
                float p = __expf(sacc[r][c] - mnew);
                sacc[r][c] = p;
                lloc += p;
            }
#pragma unroll
            for (int off = 8; off >= 1; off >>= 1)
                lloc += __shfl_xor_sync(0xffffffffu, lloc, off, 16);
            l[r] = l[r] * alpha + lloc;
            m[r] = mnew;
#pragma unroll
            for (int c = 0; c < 4; c++) o[r][c] *= alpha;
        }

        // Publish P
#pragma unroll
        for (int r = 0; r < 4; r++)
#pragma unroll
            for (int c = 0; c < 4; c++)
                sP[(ty * 4 + r) * FPAD + tx * 4 + c] = sacc[r][c];
        __syncthreads();

        // O += P @ V
#pragma unroll 4
        for (int j4 = 0; j4 < 16; j4++) {
            float4 pv[4];
#pragma unroll
            for (int r = 0; r < 4; r++)
                pv[r] = *(const float4*)&sP[(ty * 4 + r) * FPAD + j4 * 4];
#pragma unroll
            for (int jj = 0; jj < 4; jj++) {
                float4 vv = *(const float4*)&sV[(j4 * 4 + jj) * FPAD + tx * 4];
                float pr[4] = { pv[0].x, pv[1].x, pv[2].x, pv[3].x };
                if (jj == 1) { pr[0]=pv[0].y; pr[1]=pv[1].y; pr[2]=pv[2].y; pr[3]=pv[3].y; }
                if (jj == 2) { pr[0]=pv[0].z; pr[1]=pv[1].z; pr[2]=pv[2].z; pr[3]=pv[3].z; }
                if (jj == 3) { pr[0]=pv[0].w; pr[1]=pv[1].w; pr[2]=pv[2].w; pr[3]=pv[3].w; }
#pragma unroll
                for (int r = 0; r < 4; r++) {
                    o[r][0] += pr[r] * vv.x;
                    o[r][1] += pr[r] * vv.y;
                    o[r][2] += pr[r] * vv.z;
                    o[r][3] += pr[r] * vv.w;
                }
            }
        }
    }

    // Epilogue: normalize and store, (B,S,H,D)
#pragma unroll
    for (int r = 0; r < 4; r++) {
        float inv = 1.f / l[r];
        float4 v = make_float4(o[r][0] * inv, o[r][1] * inv, o[r][2] * inv, o[r][3] * inv);
        size_t gidx = (((size_t)b * S_ + q0 + ty * 4 + r) * H_ + h) * D_ + tx * 4;
        *(float4*)(Og + gidx) = v;
    }
}

// ---------------------------------------------------------------------------
extern "C" void kernel_launch(void* const* d_in, const int* in_sizes, int n_in,
                              void* d_out, int out_size)
{
    const float* x    = (const float*)d_in[0];
    const float* cosT = (const float*)d_in[1];
    const float* sinT = (const float*)d_in[2];
    const float* Wq   = (const float*)d_in[3];
    const float* Wk   = (const float*)d_in[4];
    const float* Wv   = (const float*)d_in[5];
    const float* Wo   = (const float*)d_in[6];
    float* out = (float*)d_out;

    float *Q, *K, *V, *A;
    cudaGetSymbolAddress((void**)&Q, g_Q);
    cudaGetSymbolAddress((void**)&K, g_K);
    cudaGetSymbolAddress((void**)&V, g_V);
    cudaGetSymbolAddress((void**)&A, g_A);

    // Projections
    gemm_nt_kernel<<<dim3(E_ / 128, M_ / 128), 256>>>(x, Wq, Q, M_, E_, E_);
    gemm_nt_kernel<<<dim3((HKV_ * D_) / 128, M_ / 128), 256>>>(x, Wk, K, M_, HKV_ * D_, E_);
    gemm_nt_kernel<<<dim3((HKV_ * D_) / 128, M_ / 128), 256>>>(x, Wv, V, M_, HKV_ * D_, E_);

    // RoPE
    {
        int pq = B_ * S_ * H_ * 32;
        rope_kernel<<<(pq + 255) / 256, 256>>>(Q, cosT, sinT, H_, pq);
        int pk = B_ * S_ * HKV_ * 32;
        rope_kernel<<<(pk + 255) / 256, 256>>>(K, cosT, sinT, HKV_, pk);
    }

    // Flash attention
    {
        size_t smem = 4 * 64 * FPAD * sizeof(float);  // 69632 B
        cudaFuncSetAttribute(flash_kernel, cudaFuncAttributeMaxDynamicSharedMemorySize,
                             (int)smem);
        flash_kernel<<<dim3(S_ / 64, H_, B_), dim3(16, 16), smem>>>(Q, K, V, A);
    }

    // Output projection
    gemm_nt_kernel<<<dim3(E_ / 128, M_ / 128), 256>>>(A, Wo, out, M_, E_, E_);
}

// round 4
// speedup vs baseline: 2.7094x; 2.7094x over previous
#include <cuda_runtime.h>
#include <math.h>
#include <stdint.h>

// Problem constants
#define B_  2
#define S_  2048
#define E_  2048
#define H_  32
#define HKV_ 8
#define D_  64
#define G_  4
#define M_  (B_*S_)   // 4096

// Scratch (device globals; no allocation allowed)
__device__ float g_Q[(size_t)B_*S_*H_*D_];      // (B,S,H,D)  32MB
__device__ float g_K[(size_t)B_*S_*HKV_*D_];    // (B,S,HKV,D) 8MB
__device__ float g_V[(size_t)B_*S_*HKV_*D_];    // 8MB
__device__ float g_A[(size_t)B_*S_*H_*D_];      // attention out, (B,S,H,D) == (B,S,E)

// ---------------------------------------------------------------------------
// tf32 helpers
// ---------------------------------------------------------------------------
__device__ __forceinline__ uint32_t f2tf(float x) {
    uint32_t u;
    asm("cvt.rna.tf32.f32 %0, %1;" : "=r"(u) : "f"(x));
    return u;
}

// D += A(16x8) * B(8x8), tf32 operands, f32 accumulate.
__device__ __forceinline__ void mma8(float* c, const uint32_t* a, const uint32_t* b) {
    asm volatile(
        "mma.sync.aligned.m16n8k8.row.col.f32.tf32.tf32.f32 "
        "{%0,%1,%2,%3}, {%4,%5,%6,%7}, {%8,%9}, {%0,%1,%2,%3};"
        : "+f"(c[0]), "+f"(c[1]), "+f"(c[2]), "+f"(c[3])
        : "r"(a[0]), "r"(a[1]), "r"(a[2]), "r"(a[3]), "r"(b[0]), "r"(b[1]));
}

// ---------------------------------------------------------------------------
// tf32 GEMM:  C[m][n] = sum_k A[m][k] * W[n][k]
// 128x128x32 tiles, 256 threads (8 warps, 2m x 4n), warp tile 64x32.
// SMEM holds operands in fragment-contiguous layout:
//   A frag (16x8): per-lane float4 {(r,c),(r+8,c),(r,c+4),(r+8,c+4)}, lane=(r&7)*4+(c&3)
//   B frag (8x8) : per-lane float2 {(k,n),(k+4,n)},                   lane=n*4+(k&3)
// ---------------------------------------------------------------------------
__global__ __launch_bounds__(256) void gemm_tf32(
    const float* __restrict__ A, const float* __restrict__ W,
    float* __restrict__ C, int M, int N, int K)
{
    __shared__ uint32_t sA[4096];   // 8 m-sub x 4 k-sub x 128 words
    __shared__ uint32_t sB[4096];   // 16 n-sub x 4 k-sub x 64 words

    int tid  = threadIdx.x;
    int lane = tid & 31;
    int wid  = tid >> 5;
    int wm   = wid >> 2;      // 0..1
    int wn   = wid & 3;       // 0..3
    int m0   = blockIdx.y * 128;
    int n0   = blockIdx.x * 128;

    float acc[4][4][4];
#pragma unroll
    for (int mi = 0; mi < 4; mi++)
#pragma unroll
        for (int ni = 0; ni < 4; ni++)
#pragma unroll
            for (int c = 0; c < 4; c++) acc[mi][ni][c] = 0.f;

    for (int k0 = 0; k0 < K; k0 += 32) {
        // Stage A tile 128x32 into fragment layout
#pragma unroll
        for (int i = 0; i < 4; i++) {
            int lin = tid + i * 256;          // float4 index, 1024 total
            int m   = lin >> 3;
            int kk  = (lin & 7) * 4;
            float4 v = *(const float4*)(A + (size_t)(m0 + m) * K + k0 + kk);
            int mi = m >> 4, r = m & 15, ki = kk >> 3;
            int base = ((mi * 4 + ki) * 32 + (r & 7) * 4) * 4
                     + ((r >> 3) + ((kk >> 2) & 1) * 2);
            sA[base]      = f2tf(v.x);
            sA[base + 4]  = f2tf(v.y);
            sA[base + 8]  = f2tf(v.z);
            sA[base + 12] = f2tf(v.w);
        }
        // Stage W tile 128x32
#pragma unroll
        for (int i = 0; i < 4; i++) {
            int lin = tid + i * 256;
            int n   = lin >> 3;
            int kk  = (lin & 7) * 4;
            float4 v = *(const float4*)(W + (size_t)(n0 + n) * K + k0 + kk);
            int ni = n >> 3, nr = n & 7, ki = kk >> 3;
            int base = ((ni * 4 + ki) * 32 + nr * 4) * 2 + ((kk >> 2) & 1);
            sB[base]     = f2tf(v.x);
            sB[base + 2] = f2tf(v.y);
            sB[base + 4] = f2tf(v.z);
            sB[base + 6] = f2tf(v.w);
        }
        __syncthreads();

#pragma unroll
        for (int ki = 0; ki < 4; ki++) {
            uint32_t a[4][4];
            uint32_t b[4][2];
#pragma unroll
            for (int mi = 0; mi < 4; mi++) {
                int gmi = wm * 4 + mi;
                *(uint4*)a[mi] = *(const uint4*)&sA[((gmi * 4 + ki) * 32 + lane) * 4];
            }
#pragma unroll
            for (int ni = 0; ni < 4; ni++) {
                int gni = wn * 4 + ni;
                *(uint2*)b[ni] = *(const uint2*)&sB[((gni * 4 + ki) * 32 + lane) * 2];
            }
#pragma unroll
            for (int mi = 0; mi < 4; mi++)
#pragma unroll
                for (int ni = 0; ni < 4; ni++)
                    mma8(acc[mi][ni], a[mi], b[ni]);
        }
        __syncthreads();
    }

    // Epilogue
    int gr = lane >> 2;
    int gc = (lane & 3) * 2;
#pragma unroll
    for (int mi = 0; mi < 4; mi++) {
        int row = m0 + wm * 64 + mi * 16 + gr;
#pragma unroll
        for (int ni = 0; ni < 4; ni++) {
            int col = n0 + wn * 32 + ni * 8 + gc;
            *(float2*)(C + (size_t)row * N + col) =
                make_float2(acc[mi][ni][0], acc[mi][ni][1]);
            *(float2*)(C + (size_t)(row + 8) * N + col) =
                make_float2(acc[mi][ni][2], acc[mi][ni][3]);
        }
    }
}

// ---------------------------------------------------------------------------
// RoPE in-place on (B,S,nh,D) tensor. One thread per rotation pair.
// ---------------------------------------------------------------------------
__global__ void rope_kernel(float* __restrict__ T, const float* __restrict__ cosT,
                            const float* __restrict__ sinT, int nh, int total_pairs)
{
    int idx = blockIdx.x * blockDim.x + threadIdx.x;
    if (idx >= total_pairs) return;
    int d = idx & 31;
    int h = (idx >> 5) % nh;
    int s = (idx >> 5) / nh % S_;
    int b = idx / (32 * nh * S_);
    size_t base = (((size_t)b * S_ + s) * nh + h) * D_;
    float q1 = T[base + d];
    float q2 = T[base + d + 32];
    float c  = cosT[s * D_ + d];
    float sn = sinT[s * D_ + d];
    T[base + d]      = q1 * c - q2 * sn;
    T[base + d + 32] = q2 * c + q1 * sn;
}

// ---------------------------------------------------------------------------
// Flash attention with tf32 mma. BM=128 (8 warps x 16 rows), BN=64, D=64.
// Scores/O stay in mma accumulator layout; P round-trips through SMEM in
// A-fragment layout for the PV mma. Softmax row stats reduce over lane quads.
// ---------------------------------------------------------------------------
__global__ __launch_bounds__(256) void flash_tf32(
    const float* __restrict__ Qg, const float* __restrict__ Kg,
    const float* __restrict__ Vg, float* __restrict__ Og)
{
    extern __shared__ uint32_t smf[];
    uint32_t* sQ = smf;            // 8 m-sub x 8 k-sub x 128 = 8192 words
    uint32_t* sK = sQ + 8192;      // 8 kd-sub x 8 n-sub x 64 = 4096 words
    uint32_t* sV = sK + 4096;      // 8 kt-sub x 8 d-sub x 64 = 4096 words
    uint32_t* sP = sV + 4096;      // 8 m-sub x 8 kt-sub x 128 = 8192 words

    int tid  = threadIdx.x;
    int lane = tid & 31;
    int wid  = tid >> 5;           // warp owns rows wid*16 .. wid*16+15
    int q0   = blockIdx.x * 128;
    int h    = blockIdx.y;
    int b    = blockIdx.z;
    int hk   = h >> 2;             // G=4
    int t    = lane & 3;
    int rlo  = lane >> 2;

    // Load Q tile (scaled by 1/sqrt(D)=0.125) into A-fragment layout
#pragma unroll
    for (int i = 0; i < 8; i++) {
        int lin = tid + i * 256;              // 2048 float4s
        int m   = lin >> 4;
        int d0  = (lin & 15) * 4;
        float4 v = *(const float4*)(Qg + ((((size_t)b * S_ + q0 + m) * H_ + h) * D_) + d0);
        int mi = m >> 4, r = m & 15, ki = d0 >> 3;
        int base = ((mi * 8 + ki) * 32 + (r & 7) * 4) * 4
                 + ((r >> 3) + ((d0 >> 2) & 1) * 2);
        sQ[base]      = f2tf(v.x * 0.125f);
        sQ[base + 4]  = f2tf(v.y * 0.125f);
        sQ[base + 8]  = f2tf(v.z * 0.125f);
        sQ[base + 12] = f2tf(v.w * 0.125f);
    }

    float o[8][4];
#pragma unroll
    for (int ni = 0; ni < 8; ni++)
#pragma unroll
        for (int c = 0; c < 4; c++) o[ni][c] = 0.f;
    float mlo = -INFINITY, mhi = -INFINITY;
    float llo = 0.f, lhi = 0.f;

    // precomputed base word offset within a P fragment for this thread
    int off0 = rlo * 16 + ((2 * t) & 3) * 4 + (t >> 1) * 2;

    for (int t0 = 0; t0 < S_; t0 += 64) {
        __syncthreads();
        // Load K (B-layout: k-dim = d, n-dim = kv token) and
        //      V (B-layout: k-dim = kv token, n-dim = d)
#pragma unroll
        for (int i = 0; i < 4; i++) {
            int lin = tid + i * 256;           // 1024 float4s
            int n   = lin >> 4;                // kv token in tile
            int d0  = (lin & 15) * 4;
            size_t gidx = (((size_t)b * S_ + t0 + n) * HKV_ + hk) * D_ + d0;
            float4 kv = *(const float4*)(Kg + gidx);
            {
                int ki = d0 >> 3, ni = n >> 3, nr = n & 7;
                int base = ((ki * 8 + ni) * 32 + nr * 4) * 2 + ((d0 >> 2) & 1);
                sK[base]     = f2tf(kv.x);
                sK[base + 2] = f2tf(kv.y);
                sK[base + 4] = f2tf(kv.z);
                sK[base + 6] = f2tf(kv.w);
            }
            float4 vv = *(const float4*)(Vg + gidx);
            {
                int ki = n >> 3, ni = d0 >> 3;
                int base = ((ki * 8 + ni) * 32 + (d0 & 7) * 4 + (n & 3)) * 2
                         + ((n >> 2) & 1);
                sV[base]      = f2tf(vv.x);
                sV[base + 8]  = f2tf(vv.y);
                sV[base + 16] = f2tf(vv.z);
                sV[base + 24] = f2tf(vv.w);
            }
        }
        __syncthreads();

        // S = Q K^T  (16 x 64 per warp)
        float s[8][4];
#pragma unroll
        for (int ni = 0; ni < 8; ni++)
#pragma unroll
            for (int c = 0; c < 4; c++) s[ni][c] = 0.f;

#pragma unroll
        for (int ks = 0; ks < 8; ks++) {
            uint32_t a[4];
            *(uint4*)a = *(const uint4*)&sQ[((wid * 8 + ks) * 32 + lane) * 4];
#pragma unroll
            for (int ni = 0; ni < 8; ni++) {
                uint32_t bb[2];
                *(uint2*)bb = *(const uint2*)&sK[((ks * 8 + ni) * 32 + lane) * 2];
                mma8(s[ni], a, bb);
            }
        }

        // Online softmax. Thread owns cols {ni*8 + 2t, +1} of rows rlo, rlo+8.
        float vmlo = -INFINITY, vmhi = -INFINITY;
#pragma unroll
        for (int ni = 0; ni < 8; ni++) {
            vmlo = fmaxf(vmlo, fmaxf(s[ni][0], s[ni][1]));
            vmhi = fmaxf(vmhi, fmaxf(s[ni][2], s[ni][3]));
        }
        vmlo = fmaxf(vmlo, __shfl_xor_sync(0xffffffffu, vmlo, 1));
        vmlo = fmaxf(vmlo, __shfl_xor_sync(0xffffffffu, vmlo, 2));
        vmhi = fmaxf(vmhi, __shfl_xor_sync(0xffffffffu, vmhi, 1));
        vmhi = fmaxf(vmhi, __shfl_xor_sync(0xffffffffu, vmhi, 2));

        float mnlo = fmaxf(mlo, vmlo);
        float mnhi = fmaxf(mhi, vmhi);
        float alo  = __expf(mlo - mnlo);
        float ahi  = __expf(mhi - mnhi);
        mlo = mnlo; mhi = mnhi;

        float sl = 0.f, sh = 0.f;
#pragma unroll
        for (int ni = 0; ni < 8; ni++) {
            float p0 = __expf(s[ni][0] - mnlo);
            float p1 = __expf(s[ni][1] - mnlo);
            float p2 = __expf(s[ni][2] - mnhi);
            float p3 = __expf(s[ni][3] - mnhi);
            sl += p0 + p1;
            sh += p2 + p3;
            uint32_t* pf = &sP[(wid * 8 + ni) * 128 + off0];
            pf[0] = f2tf(p0);
            pf[4] = f2tf(p1);
            pf[1] = f2tf(p2);
            pf[5] = f2tf(p3);
            o[ni][0] *= alo; o[ni][1] *= alo;
            o[ni][2] *= ahi; o[ni][3] *= ahi;
        }
        llo = llo * alo + sl;
        lhi = lhi * ahi + sh;
        __syncwarp();

        // O += P @ V
#pragma unroll
        for (int ks = 0; ks < 8; ks++) {
            uint32_t a[4];
            *(uint4*)a = *(const uint4*)&sP[((wid * 8 + ks) * 32 + lane) * 4];
#pragma unroll
            for (int ni = 0; ni < 8; ni++) {
                uint32_t bb[2];
                *(uint2*)bb = *(const uint2*)&sV[((ks * 8 + ni) * 32 + lane) * 2];
                mma8(o[ni], a, bb);
            }
        }
        // next-iteration sP writes are ordered by the loop-top __syncthreads()
    }

    // Epilogue: finish l reduction across lane quad, normalize, store
    llo += __shfl_xor_sync(0xffffffffu, llo, 1);
    llo += __shfl_xor_sync(0xffffffffu, llo, 2);
    lhi += __shfl_xor_sync(0xffffffffu, lhi, 1);
    lhi += __shfl_xor_sync(0xffffffffu, lhi, 2);
    float ilo = 1.f / llo;
    float ihi = 1.f / lhi;

    int row = q0 + wid * 16 + rlo;
#pragma unroll
    for (int ni = 0; ni < 8; ni++) {
        int d = ni * 8 + t * 2;
        size_t glo = (((size_t)b * S_ + row) * H_ + h) * D_ + d;
        *(float2*)(Og + glo) = make_float2(o[ni][0] * ilo, o[ni][1] * ilo);
        size_t ghi = (((size_t)b * S_ + row + 8) * H_ + h) * D_ + d;
        *(float2*)(Og + ghi) = make_float2(o[ni][2] * ihi, o[ni][3] * ihi);
    }
}

// ---------------------------------------------------------------------------
extern "C" void kernel_launch(void* const* d_in, const int* in_sizes, int n_in,
                              void* d_out, int out_size)
{
    const float* x    = (const float*)d_in[0];
    const float* cosT = (const float*)d_in[1];
    const float* sinT = (const float*)d_in[2];
    const float* Wq   = (const float*)d_in[3];
    const float* Wk   = (const float*)d_in[4];
    const float* Wv   = (const float*)d_in[5];
    const float* Wo   = (const float*)d_in[6];
    float* out = (float*)d_out;

    float *Q, *K, *V, *A;
    cudaGetSymbolAddress((void**)&Q, g_Q);
    cudaGetSymbolAddress((void**)&K, g_K);
    cudaGetSymbolAddress((void**)&V, g_V);
    cudaGetSymbolAddress((void**)&A, g_A);

    // Projections (tf32 tensor cores)
    gemm_tf32<<<dim3(E_ / 128, M_ / 128), 256>>>(x, Wq, Q, M_, E_, E_);
    gemm_tf32<<<dim3((HKV_ * D_) / 128, M_ / 128), 256>>>(x, Wk, K, M_, HKV_ * D_, E_);
    gemm_tf32<<<dim3((HKV_ * D_) / 128, M_ / 128), 256>>>(x, Wv, V, M_, HKV_ * D_, E_);

    // RoPE
    {
        int pq = B_ * S_ * H_ * 32;
        rope_kernel<<<(pq + 255) / 256, 256>>>(Q, cosT, sinT, H_, pq);
        int pk = B_ * S_ * HKV_ * 32;
        rope_kernel<<<(pk + 255) / 256, 256>>>(K, cosT, sinT, HKV_, pk);
    }

    // Flash attention (tf32 tensor cores)
    {
        size_t smem = 24576 * sizeof(uint32_t);  // 96 KB
        cudaFuncSetAttribute(flash_tf32, cudaFuncAttributeMaxDynamicSharedMemorySize,
                             (int)smem);
        flash_tf32<<<dim3(S_ / 128, H_, B_), 256, smem>>>(Q, K, V, A);
    }

    // Output projection
    gemm_tf32<<<dim3(E_ / 128, M_ / 128), 256>>>(A, Wo, out, M_, E_, E_);
}

// round 6
// speedup vs baseline: 4.3842x; 1.6181x over previous
#include <cuda_runtime.h>
#include <cuda_fp16.h>
#include <math.h>
#include <stdint.h>

// Problem constants
#define B_  2
#define S_  2048
#define E_  2048
#define H_  32
#define HKV_ 8
#define D_  64
#define G_  4
#define M_  (B_*S_)   // 4096

// Scratch (device globals; no allocation allowed)
__device__ float g_Q[(size_t)B_*S_*H_*D_];
__device__ float g_K[(size_t)B_*S_*HKV_*D_];
__device__ float g_V[(size_t)B_*S_*HKV_*D_];
__device__ float g_A[(size_t)B_*S_*H_*D_];

// ---------------------------------------------------------------------------
// helpers
// ---------------------------------------------------------------------------
__device__ __forceinline__ uint32_t f22h2(float lo, float hi) {
    __half2 h = __floats2half2_rn(lo, hi);   // .x = lo (low 16 bits)
    return *(uint32_t*)&h;
}

// D += A(16x16) * B(16x8), fp16 operands, f32 accumulate.
__device__ __forceinline__ void mma16(float* c, const uint32_t* a, const uint32_t* b) {
    asm volatile(
        "mma.sync.aligned.m16n8k16.row.col.f32.f16.f16.f32 "
        "{%0,%1,%2,%3}, {%4,%5,%6,%7}, {%8,%9}, {%0,%1,%2,%3};"
        : "+f"(c[0]), "+f"(c[1]), "+f"(c[2]), "+f"(c[3])
        : "r"(a[0]), "r"(a[1]), "r"(a[2]), "r"(a[3]), "r"(b[0]), "r"(b[1]));
}

// Fragment layouts in SMEM (fragment-contiguous so frag load = LDS.128 / LDS.64):
//  A frag (16 rows x 16 k): word(r, p)  [p = k/2]  ->
//      lane = (r&7)*4 + (p&3), reg = (r>>3) + 2*(p>>2), 4 words/lane
//  B frag (16 k x 8 n):     word(p, n) ->
//      lane = n*4 + (p&3), reg = p>>2, 2 words/lane

// ---------------------------------------------------------------------------
// fp16 GEMM:  C[m][n] = sum_k A[m][k] * W[n][k]
// BM=128, BN=128, BK=32; 256 threads (8 warps, 2m x 4n), warp tile 64x32.
// ---------------------------------------------------------------------------
__global__ __launch_bounds__(256) void gemm_fp16(
    const float* __restrict__ A, const float* __restrict__ W,
    float* __restrict__ C, int M, int N, int K)
{
    __shared__ uint32_t sA[2048];   // 8 m-sub x 2 k-sub x 32 lanes x 4 words
    __shared__ uint32_t sB[2048];   // 16 n-sub x 2 k-sub x 32 lanes x 2 words

    int tid  = threadIdx.x;
    int lane = tid & 31;
    int wid  = tid >> 5;
    int wm   = wid >> 2;      // 0..1
    int wn   = wid & 3;       // 0..3
    int m0   = blockIdx.y * 128;
    int n0   = blockIdx.x * 128;

    float acc[4][4][4];
#pragma unroll
    for (int mi = 0; mi < 4; mi++)
#pragma unroll
        for (int ni = 0; ni < 4; ni++)
#pragma unroll
            for (int c = 0; c < 4; c++) acc[mi][ni][c] = 0.f;

    for (int k0 = 0; k0 < K; k0 += 32) {
        // Stage A tile 128x32 -> fp16 fragments
#pragma unroll
        for (int i = 0; i < 4; i++) {
            int lin = tid + i * 256;          // 1024 float4s
            int m   = lin >> 3;
            int kq  = (lin & 7) * 4;
            float4 v = *(const float4*)(A + (size_t)(m0 + m) * K + k0 + kq);
            int mi = m >> 4, r = m & 15, ki = kq >> 4, pp = (kq >> 1) & 7;
            int base = ((mi * 2 + ki) * 32 + (r & 7) * 4 + (pp & 3)) * 4
                     + (r >> 3) + 2 * (pp >> 2);
            sA[base]     = f22h2(v.x, v.y);
            sA[base + 4] = f22h2(v.z, v.w);
        }
        // Stage W tile 128x32
#pragma unroll
        for (int i = 0; i < 4; i++) {
            int lin = tid + i * 256;
            int n   = lin >> 3;
            int kq  = (lin & 7) * 4;
            float4 v = *(const float4*)(W + (size_t)(n0 + n) * K + k0 + kq);
            int ni = n >> 3, nr = n & 7, ki = kq >> 4, pp = (kq >> 1) & 7;
            int base = ((ni * 2 + ki) * 32 + nr * 4 + (pp & 3)) * 2 + (pp >> 2);
            sB[base]     = f22h2(v.x, v.y);
            sB[base + 2] = f22h2(v.z, v.w);
        }
        __syncthreads();

#pragma unroll
        for (int ki = 0; ki < 2; ki++) {
            uint32_t a[4][4];
            uint32_t b[4][2];
#pragma unroll
            for (int mi = 0; mi < 4; mi++)
                *(uint4*)a[mi] =
                    *(const uint4*)&sA[(((wm * 4 + mi) * 2 + ki) * 32 + lane) * 4];
#pragma unroll
            for (int ni = 0; ni < 4; ni++)
                *(uint2*)b[ni] =
                    *(const uint2*)&sB[(((wn * 4 + ni) * 2 + ki) * 32 + lane) * 2];
#pragma unroll
            for (int mi = 0; mi < 4; mi++)
#pragma unroll
                for (int ni = 0; ni < 4; ni++)
                    mma16(acc[mi][ni], a[mi], b[ni]);
        }
        __syncthreads();
    }

    // Epilogue
    int gr = lane >> 2;
    int gc = (lane & 3) * 2;
#pragma unroll
    for (int mi = 0; mi < 4; mi++) {
        int row = m0 + wm * 64 + mi * 16 + gr;
#pragma unroll
        for (int ni = 0; ni < 4; ni++) {
            int col = n0 + wn * 32 + ni * 8 + gc;
            *(float2*)(C + (size_t)row * N + col) =
                make_float2(acc[mi][ni][0], acc[mi][ni][1]);
            *(float2*)(C + (size_t)(row + 8) * N + col) =
                make_float2(acc[mi][ni][2], acc[mi][ni][3]);
        }
    }
}

// ---------------------------------------------------------------------------
// RoPE in-place on (B,S,nh,D) tensor. One thread per rotation pair.
// ---------------------------------------------------------------------------
__global__ void rope_kernel(float* __restrict__ T, const float* __restrict__ cosT,
                            const float* __restrict__ sinT, int nh, int total_pairs)
{
    int idx = blockIdx.x * blockDim.x + threadIdx.x;
    if (idx >= total_pairs) return;
    int d = idx & 31;
    int h = (idx >> 5) % nh;
    int s = (idx >> 5) / nh % S_;
    int b = idx / (32 * nh * S_);
    size_t base = (((size_t)b * S_ + s) * nh + h) * D_;
    float q1 = T[base + d];
    float q2 = T[base + d + 32];
    float c  = cosT[s * D_ + d];
    float sn = sinT[s * D_ + d];
    T[base + d]      = q1 * c - q2 * sn;
    T[base + d + 32] = q2 * c + q1 * sn;
}

// ---------------------------------------------------------------------------
// Flash attention with fp16 mma. BM=128 (8 warps x 16 rows), BN=64, D=64.
// SMEM 48KB -> 2 CTAs/SM.
//   sQ: 8 m-sub x 4 kd  x 32 x 4 = 4096 words (A frags, Q pre-scaled)
//   sK: 4 kd    x 8 ntok x 32 x 2 = 2048 words (B frags)
//   sV: 4 ktok  x 8 nd   x 32 x 2 = 2048 words (B frags; halves packed per token parity)
//   sP: 8 m-sub x 4 ktok x 32 x 4 = 4096 words (A frags)
// ---------------------------------------------------------------------------
#define SQ_OFF 0
#define SK_OFF 4096
#define SV_OFF 6144
#define SP_OFF 8192
#define FLASH_SMEM (12288 * 4)

__global__ __launch_bounds__(256, 2) void flash_fp16(
    const float* __restrict__ Qg, const float* __restrict__ Kg,
    const float* __restrict__ Vg, float* __restrict__ Og)
{
    extern __shared__ uint32_t smf[];
    __half* sVh = (__half*)(smf + SV_OFF);

    int tid  = threadIdx.x;
    int lane = tid & 31;
    int wid  = tid >> 5;
    int q0   = blockIdx.x * 128;
    int h    = blockIdx.y;
    int b    = blockIdx.z;
    int hk   = h >> 2;
    int t    = lane & 3;
    int rlo  = lane >> 2;

    // Load Q tile (scaled by 1/8) into A-fragment layout
#pragma unroll
    for (int i = 0; i < 8; i++) {
        int lin = tid + i * 256;              // 2048 float4s
        int m   = lin >> 4;
        int d0  = (lin & 15) * 4;
        float4 v = *(const float4*)(Qg + ((((size_t)b * S_ + q0 + m) * H_ + h) * D_) + d0);
        int mi = m >> 4, r = m & 15, ki = d0 >> 4, pp = (d0 >> 1) & 7;
        int base = SQ_OFF + ((mi * 4 + ki) * 32 + (r & 7) * 4 + (pp & 3)) * 4
                 + (r >> 3) + 2 * (pp >> 2);
        smf[base]     = f22h2(v.x * 0.125f, v.y * 0.125f);
        smf[base + 4] = f22h2(v.z * 0.125f, v.w * 0.125f);
    }

    float o[8][4];
#pragma unroll
    for (int ni = 0; ni < 8; ni++)
#pragma unroll
        for (int c = 0; c < 4; c++) o[ni][c] = 0.f;
    float mlo = -INFINITY, mhi = -INFINITY;
    float llo = 0.f, lhi = 0.f;

    for (int t0 = 0; t0 < S_; t0 += 64) {
        __syncthreads();
        // Stage K and V tiles (64 tokens x 64 d)
#pragma unroll
        for (int i = 0; i < 4; i++) {
            int lin = tid + i * 256;           // 1024 float4s
            int n   = lin >> 4;                // kv token in tile
            int d0  = (lin & 15) * 4;
            size_t gidx = (((size_t)b * S_ + t0 + n) * HKV_ + hk) * D_ + d0;
            float4 kv = *(const float4*)(Kg + gidx);
            {   // K B-frag: k-dim = d, n-dim = token
                int ki = d0 >> 4, pp = (d0 >> 1) & 7, ni = n >> 3, nr = n & 7;
                int base = SK_OFF + ((ki * 8 + ni) * 32 + nr * 4 + (pp & 3)) * 2
                         + (pp >> 2);
                smf[base]     = f22h2(kv.x, kv.y);
                smf[base + 2] = f22h2(kv.z, kv.w);
            }
            float4 vv = *(const float4*)(Vg + gidx);
            {   // V B-frag: k-dim = token, n-dim = d; token parity selects half
                int kt = n >> 4, pp = (n >> 1) & 7, reg = pp >> 2, half = n & 1;
                int nd = d0 >> 3;
                float vals[4] = {vv.x, vv.y, vv.z, vv.w};
#pragma unroll
                for (int j = 0; j < 4; j++) {
                    int dr = (d0 & 7) + j;
                    int idx = ((kt * 8 + nd) * 32 + dr * 4 + (pp & 3)) * 2 + reg;
                    sVh[idx * 2 + half] = __float2half_rn(vals[j]);
                }
            }
        }
        __syncthreads();

        // S = Q K^T  (16 x 64 per warp)
        float s[8][4];
#pragma unroll
        for (int ni = 0; ni < 8; ni++)
#pragma unroll
            for (int c = 0; c < 4; c++) s[ni][c] = 0.f;

#pragma unroll
        for (int ks = 0; ks < 4; ks++) {
            uint32_t a[4];
            *(uint4*)a = *(const uint4*)&smf[SQ_OFF + ((wid * 4 + ks) * 32 + lane) * 4];
#pragma unroll
            for (int ni = 0; ni < 8; ni++) {
                uint32_t bb[2];
                *(uint2*)bb = *(const uint2*)&smf[SK_OFF + ((ks * 8 + ni) * 32 + lane) * 2];
                mma16(s[ni], a, bb);
            }
        }

        // Online softmax. Thread owns cols {ni*8 + 2t, +1} of rows rlo, rlo+8.
        float vmlo = -INFINITY, vmhi = -INFINITY;
#pragma unroll
        for (int ni = 0; ni < 8; ni++) {
            vmlo = fmaxf(vmlo, fmaxf(s[ni][0], s[ni][1]));
            vmhi = fmaxf(vmhi, fmaxf(s[ni][2], s[ni][3]));
        }
        vmlo = fmaxf(vmlo, __shfl_xor_sync(0xffffffffu, vmlo, 1));
        vmlo = fmaxf(vmlo, __shfl_xor_sync(0xffffffffu, vmlo, 2));
        vmhi = fmaxf(vmhi, __shfl_xor_sync(0xffffffffu, vmhi, 1));
        vmhi = fmaxf(vmhi, __shfl_xor_sync(0xffffffffu, vmhi, 2));

        float mnlo = fmaxf(mlo, vmlo);
        float mnhi = fmaxf(mhi, vmhi);
        float alo  = __expf(mlo - mnlo);
        float ahi  = __expf(mhi - mnhi);
        mlo = mnlo; mhi = mnhi;

        float sl = 0.f, sh = 0.f;
#pragma unroll
        for (int ni = 0; ni < 8; ni++) {
            float p0 = __expf(s[ni][0] - mnlo);
            float p1 = __expf(s[ni][1] - mnlo);
            float p2 = __expf(s[ni][2] - mnhi);
            float p3 = __expf(s[ni][3] - mnhi);
            sl += p0 + p1;
            sh += p2 + p3;
            // P A-frag store: own lane, kt = ni>>1, reg = 2*(ni&1) (+1 for high rows)
            int base = SP_OFF + ((wid * 4 + (ni >> 1)) * 32 + lane) * 4 + (ni & 1) * 2;
            smf[base]     = f22h2(p0, p1);
            smf[base + 1] = f22h2(p2, p3);
            o[ni][0] *= alo; o[ni][1] *= alo;
            o[ni][2] *= ahi; o[ni][3] *= ahi;
        }
        llo = llo * alo + sl;
        lhi = lhi * ahi + sh;
        __syncwarp();

        // O += P @ V
#pragma unroll
        for (int kt = 0; kt < 4; kt++) {
            uint32_t a[4];
            *(uint4*)a = *(const uint4*)&smf[SP_OFF + ((wid * 4 + kt) * 32 + lane) * 4];
#pragma unroll
            for (int ni = 0; ni < 8; ni++) {
                uint32_t bb[2];
                *(uint2*)bb = *(const uint2*)&smf[SV_OFF + ((kt * 8 + ni) * 32 + lane) * 2];
                mma16(o[ni], a, bb);
            }
        }
    }

    // Epilogue: finish l reduction across lane quad, normalize, store
    llo += __shfl_xor_sync(0xffffffffu, llo, 1);
    llo += __shfl_xor_sync(0xffffffffu, llo, 2);
    lhi += __shfl_xor_sync(0xffffffffu, lhi, 1);
    lhi += __shfl_xor_sync(0xffffffffu, lhi, 2);
    float ilo = 1.f / llo;
    float ihi = 1.f / lhi;

    int row = q0 + wid * 16 + rlo;
#pragma unroll
    for (int ni = 0; ni < 8; ni++) {
        int d = ni * 8 + t * 2;
        size_t glo = (((size_t)b * S_ + row) * H_ + h) * D_ + d;
        *(float2*)(Og + glo) = make_float2(o[ni][0] * ilo, o[ni][1] * ilo);
        size_t ghi = (((size_t)b * S_ + row + 8) * H_ + h) * D_ + d;
        *(float2*)(Og + ghi) = make_float2(o[ni][2] * ihi, o[ni][3] * ihi);
    }
}

// ---------------------------------------------------------------------------
extern "C" void kernel_launch(void* const* d_in, const int* in_sizes, int n_in,
                              void* d_out, int out_size)
{
    const float* x    = (const float*)d_in[0];
    const float* cosT = (const float*)d_in[1];
    const float* sinT = (const float*)d_in[2];
    const float* Wq   = (const float*)d_in[3];
    const float* Wk   = (const float*)d_in[4];
    const float* Wv   = (const float*)d_in[5];
    const float* Wo   = (const float*)d_in[6];
    float* out = (float*)d_out;

    float *Q, *K, *V, *A;
    cudaGetSymbolAddress((void**)&Q, g_Q);
    cudaGetSymbolAddress((void**)&K, g_K);
    cudaGetSymbolAddress((void**)&V, g_V);
    cudaGetSymbolAddress((void**)&A, g_A);

    // Projections (fp16 tensor cores, f32 accumulate)
    gemm_fp16<<<dim3(E_ / 128, M_ / 128), 256>>>(x, Wq, Q, M_, E_, E_);
    gemm_fp16<<<dim3((HKV_ * D_) / 128, M_ / 128), 256>>>(x, Wk, K, M_, HKV_ * D_, E_);
    gemm_fp16<<<dim3((HKV_ * D_) / 128, M_ / 128), 256>>>(x, Wv, V, M_, HKV_ * D_, E_);

    // RoPE
    {
        int pq = B_ * S_ * H_ * 32;
        rope_kernel<<<(pq + 255) / 256, 256>>>(Q, cosT, sinT, H_, pq);
        int pk = B_ * S_ * HKV_ * 32;
        rope_kernel<<<(pk + 255) / 256, 256>>>(K, cosT, sinT, HKV_, pk);
    }

    // Flash attention (fp16 tensor cores)
    {
        cudaFuncSetAttribute(flash_fp16, cudaFuncAttributeMaxDynamicSharedMemorySize,
                             FLASH_SMEM);
        flash_fp16<<<dim3(S_ / 128, H_, B_), 256, FLASH_SMEM>>>(Q, K, V, A);
    }

    // Output projection
    gemm_fp16<<<dim3(E_ / 128, M_ / 128), 256>>>(A, Wo, out, M_, E_, E_);
}